// round 3
// baseline (speedup 1.0000x reference)
#include <cuda_runtime.h>
#include <cstdint>
#include <cstddef>

// Problem dims
#define TT 1024
#define BB 64
#define HH 256
#define G3 768   // 3*H

// Recurrent kernel geometry: per direction, 8 clusters x 8 CTAs.
// Cluster  = one batch group of 8 batches, all 256 hidden units.
// CTA      = 32 hidden units (96 gate rows) x 8 batches.
// Thread   = 1 hidden unit x 1 batch (3 gate rows), c in register.
#define WPAD 260          // padded K stride (floats) for conflict-free LDS.128

// ---------------------------------------------------------------------------
// Static device scratch. g_gx layout: [dir][t][gate_row 0..767][b 0..63].
// ---------------------------------------------------------------------------
__device__ float g_gx[2][TT][G3][BB];   // ~402 MB

// ---------------------------------------------------------------------------
// Kernel 1: gx[d][t][g][b] = bias_d[g] + sum_i X[b][t][i] * wih_d[g][i]
// (unchanged from R2 — 64x64 tile SGEMM; optimize next round)
// ---------------------------------------------------------------------------
__global__ void __launch_bounds__(256) gx_gemm(
    const float* __restrict__ X,
    const float* __restrict__ wih_f, const float* __restrict__ bih_f,
    const float* __restrict__ bhh_f,
    const float* __restrict__ wih_b, const float* __restrict__ bih_b,
    const float* __restrict__ bhh_b)
{
    __shared__ float Xs[32][68];
    __shared__ float Ws[32][68];

    const int t  = blockIdx.x;
    const int g0 = blockIdx.y * 64;
    const int d  = blockIdx.z;
    const float* w  = d ? wih_b : wih_f;
    const float* b1 = d ? bih_b : bih_f;
    const float* b2 = d ? bhh_b : bhh_f;

    const int tid = threadIdx.x;
    const int tx  = tid & 15;
    const int ty  = tid >> 4;

    float acc[4][4] = {};

    for (int k0 = 0; k0 < 256; k0 += 32) {
        __syncthreads();
#pragma unroll
        for (int i = 0; i < 2; i++) {
            int idx = tid + i * 256;
            int row = idx >> 3;
            int kq  = idx & 7;
            float4 xv = *(const float4*)(X + ((size_t)row * TT + t) * 256 + k0 + kq * 4);
            Xs[kq * 4 + 0][row] = xv.x;
            Xs[kq * 4 + 1][row] = xv.y;
            Xs[kq * 4 + 2][row] = xv.z;
            Xs[kq * 4 + 3][row] = xv.w;
            float4 wv = *(const float4*)(w + (size_t)(g0 + row) * 256 + k0 + kq * 4);
            Ws[kq * 4 + 0][row] = wv.x;
            Ws[kq * 4 + 1][row] = wv.y;
            Ws[kq * 4 + 2][row] = wv.z;
            Ws[kq * 4 + 3][row] = wv.w;
        }
        __syncthreads();
#pragma unroll
        for (int k = 0; k < 32; k++) {
            float4 wv = *(const float4*)&Ws[k][ty * 4];
            float4 xv = *(const float4*)&Xs[k][tx * 4];
            float wr[4] = {wv.x, wv.y, wv.z, wv.w};
            float xr[4] = {xv.x, xv.y, xv.z, xv.w};
#pragma unroll
            for (int i = 0; i < 4; i++)
#pragma unroll
                for (int j = 0; j < 4; j++)
                    acc[i][j] = fmaf(wr[i], xr[j], acc[i][j]);
        }
    }

    float* outp = &g_gx[d][t][0][0];
#pragma unroll
    for (int i = 0; i < 4; i++) {
        int g = g0 + ty * 4 + i;
        float bias = b1[g] + b2[g];
        float4 v = {acc[i][0] + bias, acc[i][1] + bias,
                    acc[i][2] + bias, acc[i][3] + bias};
        *(float4*)(outp + (size_t)g * 64 + tx * 4) = v;
    }
}

// ---------------------------------------------------------------------------
// Helpers
// ---------------------------------------------------------------------------
__device__ __forceinline__ uint32_t smem_u32(const void* p) {
    uint32_t a;
    asm("{ .reg .u64 t; cvta.to.shared.u64 t, %1; cvt.u32.u64 %0, t; }"
        : "=r"(a) : "l"(p));
    return a;
}
__device__ __forceinline__ void st_cluster_f32(uint32_t laddr, int rank, float v) {
    uint32_t ra;
    asm volatile("mapa.shared::cluster.u32 %0, %1, %2;"
                 : "=r"(ra) : "r"(laddr), "r"(rank));
    asm volatile("st.shared::cluster.f32 [%0], %1;"
                 :: "r"(ra), "f"(v) : "memory");
}
__device__ __forceinline__ float fast_sigmoid(float x) {
    return 1.0f / (1.0f + __expf(-x));
}
__device__ __forceinline__ float fast_tanh(float x) {
    // 2*sigmoid(2x)-1; safe at extremes (exp->inf gives -1, exp->0 gives +1)
    return 2.0f / (1.0f + __expf(-2.0f * x)) - 1.0f;
}

// ---------------------------------------------------------------------------
// Kernel 2: persistent recurrent kernel, clusters of 8.
// grid.x = 128: blocks [0,64) dir 0, [64,128) dir 1. Within a dir, each
// aligned group of 8 blocks is one cluster (one batch group of 8 batches).
// SMEM: W_hh slice 96 rows x WPAD  +  h double buffer 2 x 8 x WPAD.
// Per step: GEMM (acc from SMEM h + SMEM w), pointwise per-thread,
// DSMEM-push new h to all 8 cluster CTAs, cluster barrier.
// ---------------------------------------------------------------------------
__global__ void __launch_bounds__(256, 1) __cluster_dims__(8, 1, 1)
lstm_rec(const float* __restrict__ whh_f,
         const float* __restrict__ whh_b,
         float* __restrict__ out)
{
    extern __shared__ float sm[];
    float* w_s = sm;                              // 96 * WPAD
    float* hb0 = sm + 96 * WPAD;                  // 8 * WPAD
    float* hb1 = hb0 + 8 * WPAD;                  // 8 * WPAD

    const int bx    = blockIdx.x;
    const int dir   = bx >> 6;
    const int crank = bx & 7;          // rank within cluster = hidden slice
    const int bg    = (bx >> 3) & 7;   // batch group within dir
    const int j0    = crank * 32;
    const float* whh = dir ? whh_b : whh_f;

    const int tid = threadIdx.x;
    const int b   = tid & 7;           // local batch 0..7
    const int jg  = tid >> 3;          // local hidden 0..31
    const int j   = j0 + jg;           // global hidden unit
    const int bG  = bg * 8 + b;        // global batch

    // Load W_hh slice: local row r = g*32 + jg' -> global row g*256 + j0 + jg'
    for (int idx = tid; idx < 96 * 256; idx += 256) {
        int r = idx >> 8, k = idx & 255;
        int grow = (r >> 5) * 256 + j0 + (r & 31);
        w_s[r * WPAD + k] = whh[(size_t)grow * 256 + k];
    }
    // Zero h buffer 0 (local only; peers never write buf consumed at s=0).
    for (int idx = tid; idx < 8 * WPAD; idx += 256) hb0[idx] = 0.0f;
    __syncthreads();

    const float* w0p = &w_s[(jg)      * WPAD];
    const float* w1p = &w_s[(32 + jg) * WPAD];
    const float* w2p = &w_s[(64 + jg) * WPAD];

    float c_reg = 0.0f;

    for (int s = 0; s < TT; s++) {
        const int t = dir ? (TT - 1 - s) : s;

        // Prefetch input contribution (independent of h).
        const float* gxt = &g_gx[dir][t][0][0];
        float gx0 = gxt[(size_t)(j)       * 64 + bG];
        float gx1 = gxt[(size_t)(256 + j) * 64 + bG];
        float gx2 = gxt[(size_t)(512 + j) * 64 + bG];

        const float* hp = ((s & 1) ? hb1 : hb0) + b * WPAD;

        float a0 = 0.0f, a1 = 0.0f, a2 = 0.0f;
#pragma unroll 4
        for (int k = 0; k < 256; k += 4) {
            float4 hv  = *(const float4*)(hp + k);
            float4 wv0 = *(const float4*)(w0p + k);
            float4 wv1 = *(const float4*)(w1p + k);
            float4 wv2 = *(const float4*)(w2p + k);
            a0 = fmaf(wv0.x, hv.x, a0); a0 = fmaf(wv0.y, hv.y, a0);
            a0 = fmaf(wv0.z, hv.z, a0); a0 = fmaf(wv0.w, hv.w, a0);
            a1 = fmaf(wv1.x, hv.x, a1); a1 = fmaf(wv1.y, hv.y, a1);
            a1 = fmaf(wv1.z, hv.z, a1); a1 = fmaf(wv1.w, hv.w, a1);
            a2 = fmaf(wv2.x, hv.x, a2); a2 = fmaf(wv2.y, hv.y, a2);
            a2 = fmaf(wv2.z, hv.z, a2); a2 = fmaf(wv2.w, hv.w, a2);
        }
        a0 += gx0; a1 += gx1; a2 += gx2;

        // Coupled-gate pointwise (thread owns hidden j, batch bG).
        float ig = fast_sigmoid(a0);
        float cg = fast_tanh(a1);
        float og = fast_sigmoid(a2);
        c_reg = (1.0f - ig) * c_reg + ig * cg;
        float h = og * fast_tanh(c_reg);

        out[(size_t)t * (BB * 2 * HH) + (size_t)bG * (2 * HH)
            + dir * HH + j] = h;

        if (s == TT - 1) {
            size_t base = (size_t)TT * BB * 2 * HH;
            out[base + (size_t)bG * (2 * HH) + dir * HH + j] = h;
            out[base + (size_t)BB * 2 * HH + (size_t)bG * (2 * HH)
                + dir * HH + j] = c_reg;
        } else {
            // Push new h to every CTA in the cluster (including self).
            float* nxt = ((s & 1) ? hb0 : hb1);
            uint32_t la = smem_u32(&nxt[b * WPAD + j]);
#pragma unroll
            for (int p = 0; p < 8; p++) st_cluster_f32(la, p, h);

            // Cluster barrier: arrive(release) orders the DSMEM stores,
            // wait(acquire) makes peer h visible for the next step.
            asm volatile("barrier.cluster.arrive.aligned;" ::: "memory");
            asm volatile("barrier.cluster.wait.aligned;" ::: "memory");
        }
    }
}

// ---------------------------------------------------------------------------
// Launch. Inputs: X, wih_f, whh_f, bih_f, bhh_f, wih_b, whh_b, bih_b, bhh_b.
// Output fp32: out[T,B,2H] ++ hn[1,B,2H] ++ cn[1,B,2H].
// ---------------------------------------------------------------------------
extern "C" void kernel_launch(void* const* d_in, const int* in_sizes, int n_in,
                              void* d_out, int out_size) {
    const float* X     = (const float*)d_in[0];
    const float* wih_f = (const float*)d_in[1];
    const float* whh_f = (const float*)d_in[2];
    const float* bih_f = (const float*)d_in[3];
    const float* bhh_f = (const float*)d_in[4];
    const float* wih_b = (const float*)d_in[5];
    const float* whh_b = (const float*)d_in[6];
    const float* bih_b = (const float*)d_in[7];
    const float* bhh_b = (const float*)d_in[8];
    float* out = (float*)d_out;

    const int rec_smem = (96 * WPAD + 2 * 8 * WPAD) * (int)sizeof(float);
    cudaFuncSetAttribute(lstm_rec, cudaFuncAttributeMaxDynamicSharedMemorySize,
                         rec_smem);

    dim3 gg(TT, G3 / 64, 2);
    gx_gemm<<<gg, 256>>>(X, wih_f, bih_f, bhh_f, wih_b, bih_b, bhh_b);
    lstm_rec<<<128, 256, rec_smem>>>(whh_f, whh_b, out);
}

// round 4
// speedup vs baseline: 1.3870x; 1.3870x over previous
#include <cuda_runtime.h>
#include <cstdint>
#include <cstddef>

// Problem dims
#define TT 1024
#define BB 64
#define HH 256
#define G3 768    // 3*H
#define HPAD 260  // padded K stride (floats): bank-conflict-free LDS.128

// Recurrent geometry: 128 CTAs = 2 dirs x 8 batch-groups x 8 hidden-slices.
// CTA tile: 96 gate rows (32 hidden x 3 gates) x 8 batches.
// Thread (jg 0..31, b 0..7): all 3 gates for one hidden unit, one batch.
// Exchange: 8 CTAs sharing a batch group swap 1KB h-slices through L2,
// synced by a per-group sense-reversing barrier (proved out in R2).

// ---------------------------------------------------------------------------
// Static device scratch.
// ---------------------------------------------------------------------------
__device__ float    g_gx[2][TT][G3][BB];       // ~402 MB input projection
__device__ float    g_h[2][2][8][8][256];      // [dir][buf][grp][b][k]
__device__ unsigned g_cnt[16 * 32];            // 128B-strided per-group counters
__device__ unsigned g_phs[16 * 32];

// ---------------------------------------------------------------------------
// Packed fp32x2 FMA (sm_103a): 2 fp32 FMA per issue, full precision.
// ---------------------------------------------------------------------------
__device__ __forceinline__ unsigned long long ffma2(
    unsigned long long a, unsigned long long b, unsigned long long c) {
    unsigned long long d;
    asm("fma.rn.f32x2 %0, %1, %2, %3;" : "=l"(d) : "l"(a), "l"(b), "l"(c));
    return d;
}
__device__ __forceinline__ float pair_sum(unsigned long long p) {
    float lo, hi;
    asm("mov.b64 {%0, %1}, %2;" : "=f"(lo), "=f"(hi) : "l"(p));
    return lo + hi;
}
__device__ __forceinline__ float fast_sigmoid(float x) {
    return 1.0f / (1.0f + __expf(-x));
}
__device__ __forceinline__ float fast_tanh(float x) {
    return 2.0f / (1.0f + __expf(-2.0f * x)) - 1.0f;
}

// Per-group sense-reversing barrier (8 arrivals), counters 128B apart.
__device__ __forceinline__ void grp_barrier(int gi) {
    __syncthreads();
    if (threadIdx.x == 0) {
        unsigned* cnt = &g_cnt[gi * 32];
        unsigned* phs = &g_phs[gi * 32];
        unsigned ph;
        asm volatile("ld.acquire.gpu.global.u32 %0, [%1];"
                     : "=r"(ph) : "l"(phs) : "memory");
        unsigned prev;
        asm volatile("atom.acq_rel.gpu.global.add.u32 %0, [%1], %2;"
                     : "=r"(prev) : "l"(cnt), "r"(1u) : "memory");
        if (prev == 7u) {
            asm volatile("st.relaxed.gpu.global.u32 [%0], %1;"
                         :: "l"(cnt), "r"(0u) : "memory");
            asm volatile("red.release.gpu.global.add.u32 [%0], %1;"
                         :: "l"(phs), "r"(1u) : "memory");
        } else {
            unsigned cur;
            do {
                asm volatile("ld.acquire.gpu.global.u32 %0, [%1];"
                             : "=r"(cur) : "l"(phs) : "memory");
            } while (cur == ph);
        }
    }
    __syncthreads();
}

// ---------------------------------------------------------------------------
// Kernel 1: gx[d][t][g][b] = bias_d[g] + sum_i X[b][t][i] * wih_d[g][i]
// (unchanged; optimize next round)
// ---------------------------------------------------------------------------
__global__ void __launch_bounds__(256) gx_gemm(
    const float* __restrict__ X,
    const float* __restrict__ wih_f, const float* __restrict__ bih_f,
    const float* __restrict__ bhh_f,
    const float* __restrict__ wih_b, const float* __restrict__ bih_b,
    const float* __restrict__ bhh_b)
{
    __shared__ float Xs[32][68];
    __shared__ float Ws[32][68];

    const int t  = blockIdx.x;
    const int g0 = blockIdx.y * 64;
    const int d  = blockIdx.z;
    const float* w  = d ? wih_b : wih_f;
    const float* b1 = d ? bih_b : bih_f;
    const float* b2 = d ? bhh_b : bhh_f;

    const int tid = threadIdx.x;
    const int tx  = tid & 15;
    const int ty  = tid >> 4;

    float acc[4][4] = {};

    for (int k0 = 0; k0 < 256; k0 += 32) {
        __syncthreads();
#pragma unroll
        for (int i = 0; i < 2; i++) {
            int idx = tid + i * 256;
            int row = idx >> 3;
            int kq  = idx & 7;
            float4 xv = *(const float4*)(X + ((size_t)row * TT + t) * 256 + k0 + kq * 4);
            Xs[kq * 4 + 0][row] = xv.x;
            Xs[kq * 4 + 1][row] = xv.y;
            Xs[kq * 4 + 2][row] = xv.z;
            Xs[kq * 4 + 3][row] = xv.w;
            float4 wv = *(const float4*)(w + (size_t)(g0 + row) * 256 + k0 + kq * 4);
            Ws[kq * 4 + 0][row] = wv.x;
            Ws[kq * 4 + 1][row] = wv.y;
            Ws[kq * 4 + 2][row] = wv.z;
            Ws[kq * 4 + 3][row] = wv.w;
        }
        __syncthreads();
#pragma unroll
        for (int k = 0; k < 32; k++) {
            float4 wv = *(const float4*)&Ws[k][ty * 4];
            float4 xv = *(const float4*)&Xs[k][tx * 4];
            float wr[4] = {wv.x, wv.y, wv.z, wv.w};
            float xr[4] = {xv.x, xv.y, xv.z, xv.w};
#pragma unroll
            for (int i = 0; i < 4; i++)
#pragma unroll
                for (int j = 0; j < 4; j++)
                    acc[i][j] = fmaf(wr[i], xr[j], acc[i][j]);
        }
    }

    float* outp = &g_gx[d][t][0][0];
#pragma unroll
    for (int i = 0; i < 4; i++) {
        int g = g0 + ty * 4 + i;
        float bias = b1[g] + b2[g];
        float4 v = {acc[i][0] + bias, acc[i][1] + bias,
                    acc[i][2] + bias, acc[i][3] + bias};
        *(float4*)(outp + (size_t)g * 64 + tx * 4) = v;
    }
}

// ---------------------------------------------------------------------------
// Kernel 2: persistent recurrent kernel. grid=128, block=256.
// ---------------------------------------------------------------------------
__global__ void __launch_bounds__(256, 1) lstm_rec(
    const float* __restrict__ whh_f,
    const float* __restrict__ whh_b,
    float* __restrict__ out)
{
    extern __shared__ float sm[];
    float* w_s = sm;                  // 96 * HPAD
    float* h_s = sm + 96 * HPAD;      // 2 * 8 * HPAD (double buffer)

    const int bx  = blockIdx.x;
    const int dir = bx >> 6;
    const int grp = (bx >> 3) & 7;
    const int sl  = bx & 7;
    const int j0  = sl * 32;
    const int gi  = dir * 8 + grp;
    const float* whh = dir ? whh_b : whh_f;

    const int tid = threadIdx.x;
    const int b   = tid & 7;
    const int jg  = tid >> 3;
    const int j   = j0 + jg;
    const int bG  = grp * 8 + b;

    // Load W_hh slice: local row r (gate g = r>>5, hidden j0 + (r&31)).
    for (int idx = tid; idx < 96 * 256; idx += 256) {
        int r = idx >> 8, k = idx & 255;
        int grow = (r >> 5) * 256 + j0 + (r & 31);
        w_s[r * HPAD + k] = whh[(size_t)grow * 256 + k];
    }
    // Zero h buffer 0 (h_0 = 0; consumed at s=0 straight from SMEM).
    for (int idx = tid; idx < 8 * HPAD; idx += 256) h_s[idx] = 0.0f;
    __syncthreads();

    const float* w0p = &w_s[(jg)      * HPAD];
    const float* w1p = &w_s[(32 + jg) * HPAD];
    const float* w2p = &w_s[(64 + jg) * HPAD];

    float c_reg = 0.0f;

    for (int s = 0; s < TT; s++) {
        const int t = dir ? (TT - 1 - s) : s;

        // Prefetch input contribution (independent of h exchange).
        const float* gxt = &g_gx[dir][t][0][0];
        float gx0 = __ldcs(&gxt[(size_t)(j)       * 64 + bG]);
        float gx1 = __ldcs(&gxt[(size_t)(256 + j) * 64 + bG]);
        float gx2 = __ldcs(&gxt[(size_t)(512 + j) * 64 + bG]);

        float* hbuf = h_s + (s & 1) * 8 * HPAD;
        if (s > 0) {
            // Stage this group's 8KB h (written by 8 peer CTAs) L2 -> SMEM.
            const float4* src = (const float4*)&g_h[dir][s & 1][grp][0][0];
#pragma unroll
            for (int rep = 0; rep < 2; rep++) {
                int fid = tid + rep * 256;          // 0..511 float4s
                int bb  = fid >> 6;                 // batch 0..7
                int kk  = (fid & 63) * 4;
                float4 v = __ldcg(src + fid);       // L2 (bypass stale L1)
                *(float4*)(hbuf + bb * HPAD + kk) = v;
            }
            __syncthreads();
        }

        // GEMM: 3 gate rows x 256 k, packed f32x2.
        const float* hp = hbuf + b * HPAD;
        unsigned long long p0 = 0ull, p1 = 0ull, p2 = 0ull;
#pragma unroll 8
        for (int k = 0; k < 256; k += 4) {
            ulonglong2 hv  = *(const ulonglong2*)(hp  + k);
            ulonglong2 wv0 = *(const ulonglong2*)(w0p + k);
            ulonglong2 wv1 = *(const ulonglong2*)(w1p + k);
            ulonglong2 wv2 = *(const ulonglong2*)(w2p + k);
            p0 = ffma2(wv0.x, hv.x, p0); p0 = ffma2(wv0.y, hv.y, p0);
            p1 = ffma2(wv1.x, hv.x, p1); p1 = ffma2(wv1.y, hv.y, p1);
            p2 = ffma2(wv2.x, hv.x, p2); p2 = ffma2(wv2.y, hv.y, p2);
        }
        float a0 = pair_sum(p0) + gx0;
        float a1 = pair_sum(p1) + gx1;
        float a2 = pair_sum(p2) + gx2;

        // Coupled-gate pointwise (thread owns hidden j, batch bG).
        float ig = fast_sigmoid(a0);
        float cg = fast_tanh(a1);
        float og = fast_sigmoid(a2);
        c_reg = (1.0f - ig) * c_reg + ig * cg;
        float h = og * fast_tanh(c_reg);

        out[(size_t)t * (BB * 2 * HH) + (size_t)bG * (2 * HH)
            + dir * HH + j] = h;

        if (s == TT - 1) {
            size_t base = (size_t)TT * BB * 2 * HH;
            out[base + (size_t)bG * (2 * HH) + dir * HH + j] = h;
            out[base + (size_t)BB * 2 * HH + (size_t)bG * (2 * HH)
                + dir * HH + j] = c_reg;
        } else {
            // Publish h slice for the group, then sync the 8 CTAs.
            g_h[dir][(s + 1) & 1][grp][b][j] = h;
            grp_barrier(gi);
        }
    }
}

// ---------------------------------------------------------------------------
// Launch. Inputs: X, wih_f, whh_f, bih_f, bhh_f, wih_b, whh_b, bih_b, bhh_b.
// Output fp32: out[T,B,2H] ++ hn[1,B,2H] ++ cn[1,B,2H].
// ---------------------------------------------------------------------------
extern "C" void kernel_launch(void* const* d_in, const int* in_sizes, int n_in,
                              void* d_out, int out_size) {
    const float* X     = (const float*)d_in[0];
    const float* wih_f = (const float*)d_in[1];
    const float* whh_f = (const float*)d_in[2];
    const float* bih_f = (const float*)d_in[3];
    const float* bhh_f = (const float*)d_in[4];
    const float* wih_b = (const float*)d_in[5];
    const float* whh_b = (const float*)d_in[6];
    const float* bih_b = (const float*)d_in[7];
    const float* bhh_b = (const float*)d_in[8];
    float* out = (float*)d_out;

    const int rec_smem = (96 * HPAD + 2 * 8 * HPAD) * (int)sizeof(float);
    cudaFuncSetAttribute(lstm_rec, cudaFuncAttributeMaxDynamicSharedMemorySize,
                         rec_smem);

    dim3 gg(TT, G3 / 64, 2);
    gx_gemm<<<gg, 256>>>(X, wih_f, bih_f, bhh_f, wih_b, bih_b, bhh_b);
    lstm_rec<<<128, 256, rec_smem>>>(whh_f, whh_b, out);
}

// round 5
// speedup vs baseline: 1.8434x; 1.3291x over previous
#include <cuda_runtime.h>
#include <cstdint>
#include <cstddef>

// Problem dims
#define TT 1024
#define BB 64
#define HH 256
#define G3 768    // 3*H

// Recurrent geometry: 128 CTAs = 2 dirs x 8 batch-groups x 8 hidden-slices.
// CTA: 32 hidden (96 gate rows) x 8 batches x K=256.
// Thread (jg 0..31, ks 0..7): 3 gate rows x 32-k slice, W_hh slice IN REGISTERS.
// Cross-lane reduction over ks via butterfly shuffle; lane ks owns batch b=ks.

// ---------------------------------------------------------------------------
// Static device scratch.
// ---------------------------------------------------------------------------
__device__ float    g_gx[2][TT][G3][BB];       // input projection, [g][b]
__device__ float    g_h[2][2][8][8][256];      // [dir][buf][grp][b][k]
__device__ unsigned g_flag[2][8][8];           // per (dir,grp,slice) step flag
__device__ unsigned g_cnt[16 * 32];            // init-barrier counters (128B apart)
__device__ unsigned g_phs[16 * 32];

// ---------------------------------------------------------------------------
// Packed fp32x2 helpers (sm_103a FFMA2: full fp32 precision, 2 FMA/issue).
// ---------------------------------------------------------------------------
__device__ __forceinline__ unsigned long long ffma2(
    unsigned long long a, unsigned long long b, unsigned long long c) {
    unsigned long long d;
    asm("fma.rn.f32x2 %0, %1, %2, %3;" : "=l"(d) : "l"(a), "l"(b), "l"(c));
    return d;
}
__device__ __forceinline__ float pair_sum(unsigned long long p) {
    float lo, hi;
    asm("mov.b64 {%0, %1}, %2;" : "=f"(lo), "=f"(hi) : "l"(p));
    return lo + hi;
}
__device__ __forceinline__ unsigned long long pack2(float lo, float hi) {
    unsigned long long p;
    asm("mov.b64 %0, {%1, %2};" : "=l"(p) : "f"(lo), "f"(hi));
    return p;
}
__device__ __forceinline__ float fast_sigmoid(float x) {
    return 1.0f / (1.0f + __expf(-x));
}
__device__ __forceinline__ float fast_tanh(float x) {
    return 2.0f / (1.0f + __expf(-2.0f * x)) - 1.0f;
}

// One-time (per launch) group barrier, replay-safe (phase monotonic).
__device__ __forceinline__ void grp_barrier_init(int gi) {
    __syncthreads();
    if (threadIdx.x == 0) {
        unsigned* cnt = &g_cnt[gi * 32];
        unsigned* phs = &g_phs[gi * 32];
        unsigned ph;
        asm volatile("ld.acquire.gpu.global.u32 %0, [%1];"
                     : "=r"(ph) : "l"(phs) : "memory");
        unsigned prev;
        asm volatile("atom.acq_rel.gpu.global.add.u32 %0, [%1], %2;"
                     : "=r"(prev) : "l"(cnt), "r"(1u) : "memory");
        if (prev == 7u) {
            asm volatile("st.relaxed.gpu.global.u32 [%0], %1;"
                         :: "l"(cnt), "r"(0u) : "memory");
            asm volatile("red.release.gpu.global.add.u32 [%0], %1;"
                         :: "l"(phs), "r"(1u) : "memory");
        } else {
            unsigned cur;
            do {
                asm volatile("ld.acquire.gpu.global.u32 %0, [%1];"
                             : "=r"(cur) : "l"(phs) : "memory");
            } while (cur == ph);
        }
    }
    __syncthreads();
}

// ---------------------------------------------------------------------------
// Kernel 1: gx[d][t][g][b] = bias_d[g] + sum_i X[b][t][i] * wih_d[g][i]
// 64x64 tile SGEMM, inner compute in packed f32x2.
// ---------------------------------------------------------------------------
__global__ void __launch_bounds__(256) gx_gemm(
    const float* __restrict__ X,
    const float* __restrict__ wih_f, const float* __restrict__ bih_f,
    const float* __restrict__ bhh_f,
    const float* __restrict__ wih_b, const float* __restrict__ bih_b,
    const float* __restrict__ bhh_b)
{
    __shared__ float Xs[32][68];
    __shared__ float Ws[32][68];

    const int t  = blockIdx.x;
    const int g0 = blockIdx.y * 64;
    const int d  = blockIdx.z;
    const float* w  = d ? wih_b : wih_f;
    const float* b1 = d ? bih_b : bih_f;
    const float* b2 = d ? bhh_b : bhh_f;

    const int tid = threadIdx.x;
    const int tx  = tid & 15;
    const int ty  = tid >> 4;

    unsigned long long acc2[4][2] = {};

    for (int k0 = 0; k0 < 256; k0 += 32) {
        __syncthreads();
#pragma unroll
        for (int i = 0; i < 2; i++) {
            int idx = tid + i * 256;
            int row = idx >> 3;
            int kq  = idx & 7;
            float4 xv = *(const float4*)(X + ((size_t)row * TT + t) * 256 + k0 + kq * 4);
            Xs[kq * 4 + 0][row] = xv.x;
            Xs[kq * 4 + 1][row] = xv.y;
            Xs[kq * 4 + 2][row] = xv.z;
            Xs[kq * 4 + 3][row] = xv.w;
            float4 wv = *(const float4*)(w + (size_t)(g0 + row) * 256 + k0 + kq * 4);
            Ws[kq * 4 + 0][row] = wv.x;
            Ws[kq * 4 + 1][row] = wv.y;
            Ws[kq * 4 + 2][row] = wv.z;
            Ws[kq * 4 + 3][row] = wv.w;
        }
        __syncthreads();
#pragma unroll
        for (int k = 0; k < 32; k++) {
            float4 wv = *(const float4*)&Ws[k][ty * 4];
            ulonglong2 xp = *(const ulonglong2*)&Xs[k][tx * 4];
            float wr[4] = {wv.x, wv.y, wv.z, wv.w};
#pragma unroll
            for (int i = 0; i < 4; i++) {
                unsigned long long wd = pack2(wr[i], wr[i]);
                acc2[i][0] = ffma2(wd, xp.x, acc2[i][0]);
                acc2[i][1] = ffma2(wd, xp.y, acc2[i][1]);
            }
        }
    }

    float* outp = &g_gx[d][t][0][0];
#pragma unroll
    for (int i = 0; i < 4; i++) {
        int g = g0 + ty * 4 + i;
        float bias = b1[g] + b2[g];
        float v0, v1, v2, v3;
        asm("mov.b64 {%0, %1}, %2;" : "=f"(v0), "=f"(v1) : "l"(acc2[i][0]));
        asm("mov.b64 {%0, %1}, %2;" : "=f"(v2), "=f"(v3) : "l"(acc2[i][1]));
        float4 v = {v0 + bias, v1 + bias, v2 + bias, v3 + bias};
        *(float4*)(outp + (size_t)g * 64 + tx * 4) = v;
    }
}

// ---------------------------------------------------------------------------
// Kernel 2: persistent recurrent kernel. grid=128, block=256.
// SMEM: h double buffer only, 2 x 8 x 256 floats (16KB), XOR-swizzled chunks.
// ---------------------------------------------------------------------------
__global__ void __launch_bounds__(256, 1) lstm_rec(
    const float* __restrict__ whh_f,
    const float* __restrict__ whh_b,
    float* __restrict__ out)
{
    __shared__ float hs[2][8][256];

    const int bx  = blockIdx.x;
    const int dir = bx >> 6;
    const int grp = (bx >> 3) & 7;
    const int sl  = bx & 7;
    const int j0  = sl * 32;
    const int gi  = dir * 8 + grp;
    const float* whh = dir ? whh_b : whh_f;

    const int tid  = threadIdx.x;
    const int lane = tid & 31;
    const int warp = tid >> 5;
    const int jg   = warp * 4 + (lane >> 3);   // hidden within slice 0..31
    const int ks   = lane & 7;                 // k-slice 0..7
    const int j    = j0 + jg;
    const int bG   = grp * 8 + ks;             // this thread's output batch

    // --- Load W_hh slice into REGISTERS: 3 rows x 32 k = 48 f32x2. ---
    unsigned long long w0r[16], w1r[16], w2r[16];
#pragma unroll
    for (int g = 0; g < 3; g++) {
        const float* base = whh + (size_t)(g * 256 + j) * 256 + ks * 32;
        unsigned long long* dst = (g == 0) ? w0r : (g == 1) ? w1r : w2r;
#pragma unroll
        for (int c = 0; c < 8; c++) {
            ulonglong2 wv = *(const ulonglong2*)(base + c * 4);
            dst[2 * c]     = wv.x;
            dst[2 * c + 1] = wv.y;
        }
    }

    // Zero h buffer 0 (h_0 = 0) and reset this CTA's flag; then group barrier
    // so no peer can publish flag=1 before all resets land (replay safety).
    for (int idx = tid; idx < 8 * 256; idx += 256) ((float*)hs)[idx] = 0.0f;
    if (tid == 0)
        asm volatile("st.relaxed.gpu.global.u32 [%0], %1;"
                     :: "l"(&g_flag[dir][grp][sl]), "r"(0u) : "memory");
    grp_barrier_init(gi);

    float c_reg = 0.0f;

    for (int s = 0; s < TT; s++) {
        const int t = dir ? (TT - 1 - s) : s;

        // Prefetch input contribution (DRAM, independent of h exchange).
        const float* gxt = &g_gx[dir][t][0][0];
        float gx0 = __ldcs(&gxt[(size_t)(j)       * 64 + bG]);
        float gx1 = __ldcs(&gxt[(size_t)(256 + j) * 64 + bG]);
        float gx2 = __ldcs(&gxt[(size_t)(512 + j) * 64 + bG]);

        float* hbuf = &hs[s & 1][0][0];
        if (s > 0) {
            // Wait for all 8 producers of step s-1 (flag >= s).
            if (tid < 8) {
                const unsigned* f = &g_flag[dir][grp][tid];
                unsigned v;
                do {
                    asm volatile("ld.acquire.gpu.global.u32 %0, [%1];"
                                 : "=r"(v) : "l"(f) : "memory");
                } while (v < (unsigned)s);
            }
            __syncthreads();
            // Stage 8KB h from L2 into SMEM with XOR-swizzled chunk layout.
            const float4* src = (const float4*)&g_h[dir][s & 1][grp][0][0];
#pragma unroll
            for (int rep = 0; rep < 2; rep++) {
                int fid = tid + rep * 256;          // 0..511
                int b   = fid >> 6;
                int q   = fid & 63;
                int seg = q >> 3;
                int c   = q & 7;
                float4 v = __ldcg(src + fid);
                *(float4*)(hbuf + b * 256 + seg * 32 + ((c ^ seg) & 7) * 4) = v;
            }
            __syncthreads();
        }

        // --- GEMM: 3 rows x 8 batches x 32 k, weights in regs. ---
        float a0[8], a1[8], a2[8];
#pragma unroll
        for (int b = 0; b < 8; b++) {
            const float* hp = hbuf + b * 256 + ks * 32;
            unsigned long long A0 = 0ull, A1 = 0ull, A2 = 0ull;
#pragma unroll
            for (int c = 0; c < 8; c++) {
                ulonglong2 hv = *(const ulonglong2*)(hp + ((c ^ ks) & 7) * 4);
                A0 = ffma2(w0r[2 * c], hv.x, A0);
                A0 = ffma2(w0r[2 * c + 1], hv.y, A0);
                A1 = ffma2(w1r[2 * c], hv.x, A1);
                A1 = ffma2(w1r[2 * c + 1], hv.y, A1);
                A2 = ffma2(w2r[2 * c], hv.x, A2);
                A2 = ffma2(w2r[2 * c + 1], hv.y, A2);
            }
            a0[b] = pair_sum(A0);
            a1[b] = pair_sum(A1);
            a2[b] = pair_sum(A2);
        }

        // --- Butterfly reduce-scatter over ks: lane ks ends with batch b=ks. ---
        const bool hi4 = (ks & 4) != 0;
        float t0[4], t1[4], t2[4];
#pragma unroll
        for (int i = 0; i < 4; i++) {
            float s0 = hi4 ? a0[i] : a0[i + 4];
            float s1 = hi4 ? a1[i] : a1[i + 4];
            float s2 = hi4 ? a2[i] : a2[i + 4];
            t0[i] = (hi4 ? a0[i + 4] : a0[i]) + __shfl_xor_sync(0xffffffffu, s0, 4);
            t1[i] = (hi4 ? a1[i + 4] : a1[i]) + __shfl_xor_sync(0xffffffffu, s1, 4);
            t2[i] = (hi4 ? a2[i + 4] : a2[i]) + __shfl_xor_sync(0xffffffffu, s2, 4);
        }
        const bool hi2 = (ks & 2) != 0;
        float u0[2], u1[2], u2[2];
#pragma unroll
        for (int i = 0; i < 2; i++) {
            float s0 = hi2 ? t0[i] : t0[i + 2];
            float s1 = hi2 ? t1[i] : t1[i + 2];
            float s2 = hi2 ? t2[i] : t2[i + 2];
            u0[i] = (hi2 ? t0[i + 2] : t0[i]) + __shfl_xor_sync(0xffffffffu, s0, 2);
            u1[i] = (hi2 ? t1[i + 2] : t1[i]) + __shfl_xor_sync(0xffffffffu, s1, 2);
            u2[i] = (hi2 ? t2[i + 2] : t2[i]) + __shfl_xor_sync(0xffffffffu, s2, 2);
        }
        const bool hi1 = (ks & 1) != 0;
        {
            float s0 = hi1 ? u0[0] : u0[1];
            float s1 = hi1 ? u1[0] : u1[1];
            float s2 = hi1 ? u2[0] : u2[1];
            float f0 = (hi1 ? u0[1] : u0[0]) + __shfl_xor_sync(0xffffffffu, s0, 1);
            float f1 = (hi1 ? u1[1] : u1[0]) + __shfl_xor_sync(0xffffffffu, s1, 1);
            float f2 = (hi1 ? u2[1] : u2[0]) + __shfl_xor_sync(0xffffffffu, s2, 1);

            f0 += gx0; f1 += gx1; f2 += gx2;

            // Coupled-gate pointwise for (hidden j, batch bG).
            float ig = fast_sigmoid(f0);
            float cg = fast_tanh(f1);
            float og = fast_sigmoid(f2);
            c_reg = (1.0f - ig) * c_reg + ig * cg;
            float h = og * fast_tanh(c_reg);

            if (s == TT - 1) {
                out[(size_t)t * (BB * 2 * HH) + (size_t)bG * (2 * HH)
                    + dir * HH + j] = h;
                size_t base = (size_t)TT * BB * 2 * HH;
                out[base + (size_t)bG * (2 * HH) + dir * HH + j] = h;
                out[base + (size_t)BB * 2 * HH + (size_t)bG * (2 * HH)
                    + dir * HH + j] = c_reg;
            } else {
                // Publish h, release flag, then stream the output write.
                g_h[dir][(s + 1) & 1][grp][ks][j] = h;
                __syncthreads();
                if (tid == 0)
                    asm volatile("st.release.gpu.global.u32 [%0], %1;"
                                 :: "l"(&g_flag[dir][grp][sl]),
                                    "r"((unsigned)(s + 1)) : "memory");
                out[(size_t)t * (BB * 2 * HH) + (size_t)bG * (2 * HH)
                    + dir * HH + j] = h;
            }
        }
    }
}

// ---------------------------------------------------------------------------
// Launch. Inputs: X, wih_f, whh_f, bih_f, bhh_f, wih_b, whh_b, bih_b, bhh_b.
// Output fp32: out[T,B,2H] ++ hn[1,B,2H] ++ cn[1,B,2H].
// ---------------------------------------------------------------------------
extern "C" void kernel_launch(void* const* d_in, const int* in_sizes, int n_in,
                              void* d_out, int out_size) {
    const float* X     = (const float*)d_in[0];
    const float* wih_f = (const float*)d_in[1];
    const float* whh_f = (const float*)d_in[2];
    const float* bih_f = (const float*)d_in[3];
    const float* bhh_f = (const float*)d_in[4];
    const float* wih_b = (const float*)d_in[5];
    const float* whh_b = (const float*)d_in[6];
    const float* bih_b = (const float*)d_in[7];
    const float* bhh_b = (const float*)d_in[8];
    float* out = (float*)d_out;

    dim3 gg(TT, G3 / 64, 2);
    gx_gemm<<<gg, 256>>>(X, wih_f, bih_f, bhh_f, wih_b, bih_b, bhh_b);
    lstm_rec<<<128, 256>>>(whh_f, whh_b, out);
}

// round 6
// speedup vs baseline: 2.2974x; 1.2463x over previous
#include <cuda_runtime.h>
#include <cstdint>
#include <cstddef>

// Problem dims
#define TT 1024
#define BB 64
#define HH 256
#define WPADI 260   // wih SMEM row stride (floats)

// Fully fused single persistent kernel.
// 128 CTAs = 2 dirs x 8 batch-groups x 8 hidden-slices.
// CTA: 32 hidden (96 gate rows) x 8 batches, K=256 for BOTH GEMMs.
// Thread (jg 0..31, ks 0..7): 3 gate rows x 32-k slice.
//   W_hh slice: registers (96 floats = 48 f32x2).
//   W_ih slice: SMEM (LDS per step, amortized via idle issue slots).
//   x[t]: SMEM double buffer, prefetched one step ahead (DRAM latency hidden).
// gx GEMM runs BEFORE the peer-flag wait (independent of h) and shares
// accumulators with the recurrent GEMM; one shuffle reduce-scatter ends with
// lane ks owning batch b=ks.

// ---------------------------------------------------------------------------
// Static device scratch.
// ---------------------------------------------------------------------------
__device__ float    g_h[2][2][8][8][256];   // [dir][buf][grp][b][k]
__device__ unsigned g_flag[2][8][8];        // per (dir,grp,slice) step flag
__device__ unsigned g_cnt[16 * 32];         // init barrier (128B-strided)
__device__ unsigned g_phs[16 * 32];

// ---------------------------------------------------------------------------
// Packed fp32x2 helpers (full fp32 precision, 2 FMA per issue on sm_103a).
// ---------------------------------------------------------------------------
__device__ __forceinline__ unsigned long long ffma2(
    unsigned long long a, unsigned long long b, unsigned long long c) {
    unsigned long long d;
    asm("fma.rn.f32x2 %0, %1, %2, %3;" : "=l"(d) : "l"(a), "l"(b), "l"(c));
    return d;
}
__device__ __forceinline__ float pair_sum(unsigned long long p) {
    float lo, hi;
    asm("mov.b64 {%0, %1}, %2;" : "=f"(lo), "=f"(hi) : "l"(p));
    return lo + hi;
}
__device__ __forceinline__ float fast_sigmoid(float x) {
    return 1.0f / (1.0f + __expf(-x));
}
__device__ __forceinline__ float fast_tanh(float x) {
    return 2.0f / (1.0f + __expf(-2.0f * x)) - 1.0f;
}

// One-time replay-safe group barrier (phase monotonic across replays).
__device__ __forceinline__ void grp_barrier_init(int gi) {
    __syncthreads();
    if (threadIdx.x == 0) {
        unsigned* cnt = &g_cnt[gi * 32];
        unsigned* phs = &g_phs[gi * 32];
        unsigned ph;
        asm volatile("ld.acquire.gpu.global.u32 %0, [%1];"
                     : "=r"(ph) : "l"(phs) : "memory");
        unsigned prev;
        asm volatile("atom.acq_rel.gpu.global.add.u32 %0, [%1], %2;"
                     : "=r"(prev) : "l"(cnt), "r"(1u) : "memory");
        if (prev == 7u) {
            asm volatile("st.relaxed.gpu.global.u32 [%0], %1;"
                         :: "l"(cnt), "r"(0u) : "memory");
            asm volatile("red.release.gpu.global.add.u32 [%0], %1;"
                         :: "l"(phs), "r"(1u) : "memory");
        } else {
            unsigned cur;
            do {
                asm volatile("ld.acquire.gpu.global.u32 %0, [%1];"
                             : "=r"(cur) : "l"(phs) : "memory");
            } while (cur == ph);
        }
    }
    __syncthreads();
}

// ---------------------------------------------------------------------------
// Fused persistent LSTM kernel. grid=128, block=256.
// SMEM: wih_s[96][WPADI] + hs[2][8][256] + xs[2][8][256]  (~116 KB)
// ---------------------------------------------------------------------------
__global__ void __launch_bounds__(256, 1) lstm_fused(
    const float* __restrict__ X,
    const float* __restrict__ wih_f, const float* __restrict__ whh_f,
    const float* __restrict__ bih_f, const float* __restrict__ bhh_f,
    const float* __restrict__ wih_b, const float* __restrict__ whh_b,
    const float* __restrict__ bih_b, const float* __restrict__ bhh_b,
    float* __restrict__ out)
{
    extern __shared__ float sm[];
    float* wih_s = sm;                       // 96 * WPADI
    float* hs    = sm + 96 * WPADI;          // 2 * 8 * 256
    float* xs    = hs + 2 * 8 * 256;         // 2 * 8 * 256

    const int bx  = blockIdx.x;
    const int dir = bx >> 6;
    const int grp = (bx >> 3) & 7;
    const int sl  = bx & 7;
    const int j0  = sl * 32;
    const int gi  = dir * 8 + grp;

    const float* whh = dir ? whh_b : whh_f;
    const float* wih = dir ? wih_b : wih_f;
    const float* bih = dir ? bih_b : bih_f;
    const float* bhh = dir ? bhh_b : bhh_f;

    const int tid  = threadIdx.x;
    const int lane = tid & 31;
    const int warp = tid >> 5;
    const int jg   = warp * 4 + (lane >> 3);   // hidden within slice 0..31
    const int ks   = lane & 7;                 // k-slice 0..7
    const int j    = j0 + jg;
    const int bG   = grp * 8 + ks;             // this thread's output batch
    const int col  = ks * 32;                  // k-slice base column

    // --- W_hh slice into REGISTERS: 3 rows x 32 k = 48 f32x2. ---
    unsigned long long w0r[16], w1r[16], w2r[16];
#pragma unroll
    for (int g = 0; g < 3; g++) {
        const float* base = whh + (size_t)(g * 256 + j) * 256 + col;
        unsigned long long* dst = (g == 0) ? w0r : (g == 1) ? w1r : w2r;
#pragma unroll
        for (int c = 0; c < 8; c++) {
            ulonglong2 wv = *(const ulonglong2*)(base + c * 4);
            dst[2 * c]     = wv.x;
            dst[2 * c + 1] = wv.y;
        }
    }

    // --- W_ih slice into SMEM with XOR-swizzled 16B chunks. ---
    for (int idx = tid; idx < 96 * 64; idx += 256) {
        int r = idx >> 6, q = idx & 63;
        int seg = q >> 3, c = q & 7;
        int grow = (r >> 5) * 256 + j0 + (r & 31);
        float4 v = *(const float4*)(wih + (size_t)grow * 256 + q * 4);
        *(float4*)(wih_s + r * WPADI + seg * 32 + ((c ^ seg) & 7) * 4) = v;
    }

    // Bias (added once, post-reduce, by the owning lane).
    const float bias0 = bih[j]       + bhh[j];
    const float bias1 = bih[256 + j] + bhh[256 + j];
    const float bias2 = bih[512 + j] + bhh[512 + j];

    // Zero h buffer 0; stage x for t0 into xs buffer 0.
    for (int idx = tid; idx < 8 * 256; idx += 256) hs[idx] = 0.0f;
    {
        const int t0 = dir ? (TT - 1) : 0;
#pragma unroll
        for (int rep = 0; rep < 2; rep++) {
            int fid = tid + rep * 256;
            int b = fid >> 6, q = fid & 63;
            int seg = q >> 3, c = q & 7;
            float4 v = __ldcg((const float4*)(
                X + ((size_t)(grp * 8 + b) * TT + t0) * 256 + q * 4));
            *(float4*)(xs + b * 256 + seg * 32 + ((c ^ seg) & 7) * 4) = v;
        }
    }
    // Reset flag; group barrier (replay safety: no peer publishes before resets).
    if (tid == 0)
        asm volatile("st.relaxed.gpu.global.u32 [%0], %1;"
                     :: "l"(&g_flag[dir][grp][sl]), "r"(0u) : "memory");
    grp_barrier_init(gi);

    float c_reg = 0.0f;

    for (int s = 0; s < TT; s++) {
        const int t = dir ? (TT - 1 - s) : s;

        // --- Prefetch x[t(s+1)] into registers (DRAM latency hidden). ---
        float4 xpa, xpb;
        if (s + 1 < TT) {
            const int tn = dir ? (t - 1) : (t + 1);
            int fid0 = tid, fid1 = tid + 256;
            xpa = __ldcg((const float4*)(
                X + ((size_t)(grp * 8 + (fid0 >> 6)) * TT + tn) * 256 + (fid0 & 63) * 4));
            xpb = __ldcg((const float4*)(
                X + ((size_t)(grp * 8 + (fid1 >> 6)) * TT + tn) * 256 + (fid1 & 63) * 4));
        }

        // --- gx GEMM: W_ih (SMEM) x x[t] (SMEM) — independent of peers. ---
        unsigned long long P0[8], P1[8], P2[8];
#pragma unroll
        for (int b = 0; b < 8; b++) { P0[b] = 0ull; P1[b] = 0ull; P2[b] = 0ull; }

        const float* xb = xs + (s & 1) * 2048;
#pragma unroll
        for (int c = 0; c < 8; c++) {
            const int off = col + ((c ^ ks) & 7) * 4;
            ulonglong2 w0 = *(const ulonglong2*)(wih_s + (jg)      * WPADI + off);
            ulonglong2 w1 = *(const ulonglong2*)(wih_s + (32 + jg) * WPADI + off);
            ulonglong2 w2 = *(const ulonglong2*)(wih_s + (64 + jg) * WPADI + off);
#pragma unroll
            for (int b = 0; b < 8; b++) {
                ulonglong2 hv = *(const ulonglong2*)(xb + b * 256 + off);
                P0[b] = ffma2(w0.x, hv.x, P0[b]);
                P1[b] = ffma2(w1.x, hv.x, P1[b]);
                P2[b] = ffma2(w2.x, hv.x, P2[b]);
                P0[b] = ffma2(w0.y, hv.y, P0[b]);
                P1[b] = ffma2(w1.y, hv.y, P1[b]);
                P2[b] = ffma2(w2.y, hv.y, P2[b]);
            }
        }

        // --- Wait for peers' h(s-1), stage 8KB L2 -> SMEM. ---
        float* hb = hs + (s & 1) * 2048;
        if (s > 0) {
            if (tid < 8) {
                const unsigned* f = &g_flag[dir][grp][tid];
                unsigned v;
                do {
                    asm volatile("ld.acquire.gpu.global.u32 %0, [%1];"
                                 : "=r"(v) : "l"(f) : "memory");
                } while (v < (unsigned)s);
            }
            __syncthreads();
            const float4* src = (const float4*)&g_h[dir][s & 1][grp][0][0];
#pragma unroll
            for (int rep = 0; rep < 2; rep++) {
                int fid = tid + rep * 256;
                int b = fid >> 6, q = fid & 63;
                int seg = q >> 3, c = q & 7;
                float4 v = __ldcg(src + fid);
                *(float4*)(hb + b * 256 + seg * 32 + ((c ^ seg) & 7) * 4) = v;
            }
            __syncthreads();
        }

        // --- Recurrent GEMM: W_hh (regs) x h (SMEM), same accumulators. ---
#pragma unroll
        for (int b = 0; b < 8; b++) {
            const float* hp = hb + b * 256 + col;
#pragma unroll
            for (int c = 0; c < 8; c++) {
                ulonglong2 hv = *(const ulonglong2*)(hp + ((c ^ ks) & 7) * 4);
                P0[b] = ffma2(w0r[2 * c], hv.x, P0[b]);
                P1[b] = ffma2(w1r[2 * c], hv.x, P1[b]);
                P2[b] = ffma2(w2r[2 * c], hv.x, P2[b]);
                P0[b] = ffma2(w0r[2 * c + 1], hv.y, P0[b]);
                P1[b] = ffma2(w1r[2 * c + 1], hv.y, P1[b]);
                P2[b] = ffma2(w2r[2 * c + 1], hv.y, P2[b]);
            }
        }

        float a0[8], a1[8], a2[8];
#pragma unroll
        for (int b = 0; b < 8; b++) {
            a0[b] = pair_sum(P0[b]);
            a1[b] = pair_sum(P1[b]);
            a2[b] = pair_sum(P2[b]);
        }

        // --- Butterfly reduce-scatter over ks: lane ks owns batch b=ks. ---
        const bool hi4 = (ks & 4) != 0;
        float t0a[4], t1a[4], t2a[4];
#pragma unroll
        for (int i = 0; i < 4; i++) {
            float s0 = hi4 ? a0[i] : a0[i + 4];
            float s1 = hi4 ? a1[i] : a1[i + 4];
            float s2 = hi4 ? a2[i] : a2[i + 4];
            t0a[i] = (hi4 ? a0[i + 4] : a0[i]) + __shfl_xor_sync(0xffffffffu, s0, 4);
            t1a[i] = (hi4 ? a1[i + 4] : a1[i]) + __shfl_xor_sync(0xffffffffu, s1, 4);
            t2a[i] = (hi4 ? a2[i + 4] : a2[i]) + __shfl_xor_sync(0xffffffffu, s2, 4);
        }
        const bool hi2 = (ks & 2) != 0;
        float u0[2], u1[2], u2[2];
#pragma unroll
        for (int i = 0; i < 2; i++) {
            float s0 = hi2 ? t0a[i] : t0a[i + 2];
            float s1 = hi2 ? t1a[i] : t1a[i + 2];
            float s2 = hi2 ? t2a[i] : t2a[i + 2];
            u0[i] = (hi2 ? t0a[i + 2] : t0a[i]) + __shfl_xor_sync(0xffffffffu, s0, 2);
            u1[i] = (hi2 ? t1a[i + 2] : t1a[i]) + __shfl_xor_sync(0xffffffffu, s1, 2);
            u2[i] = (hi2 ? t2a[i + 2] : t2a[i]) + __shfl_xor_sync(0xffffffffu, s2, 2);
        }
        const bool hi1 = (ks & 1) != 0;
        float s0 = hi1 ? u0[0] : u0[1];
        float s1 = hi1 ? u1[0] : u1[1];
        float s2 = hi1 ? u2[0] : u2[1];
        float f0 = (hi1 ? u0[1] : u0[0]) + __shfl_xor_sync(0xffffffffu, s0, 1);
        float f1 = (hi1 ? u1[1] : u1[0]) + __shfl_xor_sync(0xffffffffu, s1, 1);
        float f2 = (hi1 ? u2[1] : u2[0]) + __shfl_xor_sync(0xffffffffu, s2, 1);

        f0 += bias0; f1 += bias1; f2 += bias2;

        // --- Coupled-gate pointwise for (hidden j, batch bG). ---
        float ig = fast_sigmoid(f0);
        float cg = fast_tanh(f1);
        float og = fast_sigmoid(f2);
        c_reg = (1.0f - ig) * c_reg + ig * cg;
        float h = og * fast_tanh(c_reg);

        if (s == TT - 1) {
            out[(size_t)t * (BB * 2 * HH) + (size_t)bG * (2 * HH)
                + dir * HH + j] = h;
            size_t base = (size_t)TT * BB * 2 * HH;
            out[base + (size_t)bG * (2 * HH) + dir * HH + j] = h;
            out[base + (size_t)BB * 2 * HH + (size_t)bG * (2 * HH)
                + dir * HH + j] = c_reg;
        } else {
            // Publish h slice; store prefetched x into next buffer.
            g_h[dir][(s + 1) & 1][grp][ks][j] = h;
            float* xn = xs + ((s + 1) & 1) * 2048;
            {
                int fid = tid, q = fid & 63, seg = q >> 3, c = q & 7;
                *(float4*)(xn + (fid >> 6) * 256 + seg * 32 + ((c ^ seg) & 7) * 4) = xpa;
            }
            {
                int fid = tid + 256, q = fid & 63, seg = q >> 3, c = q & 7;
                *(float4*)(xn + (fid >> 6) * 256 + seg * 32 + ((c ^ seg) & 7) * 4) = xpb;
            }
            __syncthreads();   // orders g_h stores (flag) and xs stores (next read)
            if (tid == 0)
                asm volatile("st.release.gpu.global.u32 [%0], %1;"
                             :: "l"(&g_flag[dir][grp][sl]),
                                "r"((unsigned)(s + 1)) : "memory");
            out[(size_t)t * (BB * 2 * HH) + (size_t)bG * (2 * HH)
                + dir * HH + j] = h;
        }
    }
}

// ---------------------------------------------------------------------------
// Launch. Inputs: X, wih_f, whh_f, bih_f, bhh_f, wih_b, whh_b, bih_b, bhh_b.
// Output fp32: out[T,B,2H] ++ hn[1,B,2H] ++ cn[1,B,2H].
// ---------------------------------------------------------------------------
extern "C" void kernel_launch(void* const* d_in, const int* in_sizes, int n_in,
                              void* d_out, int out_size) {
    const float* X     = (const float*)d_in[0];
    const float* wih_f = (const float*)d_in[1];
    const float* whh_f = (const float*)d_in[2];
    const float* bih_f = (const float*)d_in[3];
    const float* bhh_f = (const float*)d_in[4];
    const float* wih_b = (const float*)d_in[5];
    const float* whh_b = (const float*)d_in[6];
    const float* bih_b = (const float*)d_in[7];
    const float* bhh_b = (const float*)d_in[8];
    float* out = (float*)d_out;

    const int smem = (96 * WPADI + 2 * 8 * 256 + 2 * 8 * 256) * (int)sizeof(float);
    cudaFuncSetAttribute(lstm_fused, cudaFuncAttributeMaxDynamicSharedMemorySize,
                         smem);

    lstm_fused<<<128, 256, smem>>>(X, wih_f, whh_f, bih_f, bhh_f,
                                   wih_b, whh_b, bih_b, bhh_b, out);
}